// round 15
// baseline (speedup 1.0000x reference)
#include <cuda_runtime.h>
#include <cub/cub.cuh>
#include <cstdint>

#define MAXP 10
#define MAXV 160000
#define NCAP (1 << 21)
#define IDX_BITS 21
#define IDX_MASK ((1u << IDX_BITS) - 1u)
#define BBITS 20
#define NBUCKET (1u << BBITS)
#define BSHIFT (32 - BBITS)   // 12: bucket = flipped_key >> 12

// Output layout (tuple order): voxels | coors | num_points | voxel_num
#define OFF_VOX   0
#define OFF_COORS 8000000
#define OFF_CNT   8480000
#define OFF_VNUM  8640000

// ---- device scratch (static globals: allowed; no runtime allocation) ----
__device__ unsigned long long g_val[NCAP];      // per-point (lin << 21 | idx)
__device__ unsigned long long g_sorted[NCAP];   // bucket-sorted, then locally sorted
__device__ int g_bcnt[NBUCKET];                 // bucket histogram (zeroed per run)
__device__ int g_boff[NBUCKET];                 // exclusive offsets; mutated to ENDS
__device__ int g_fidx[NCAP];                    // head flag in ORIGINAL index order
__device__ int g_rank[NCAP];                    // exclusive prefix sum of g_fidx
__device__ int g_cnt[MAXV];                     // cleared inside passK
__device__ __align__(256) unsigned char g_cubtmp[4u << 20];

// Flipped (sign-bit-toggled) wrapped int32 key: unsigned order == signed order.
__device__ __forceinline__ unsigned fkey_of(unsigned long long v, unsigned n) {
    return ((unsigned)(v >> IDX_BITS) * n + (unsigned)(v & IDX_MASK)) ^ 0x80000000u;
}

// IEEE f32 quantization (bit-matches XLA CPU float32; immune to fast-math).
__device__ __forceinline__ void grid_dims(const float* __restrict__ vs,
                                          const float* __restrict__ cr,
                                          int& gx, int& gy, int& gz) {
    gx = (int)rintf(__fdiv_rn(__fsub_rn(cr[3], cr[0]), vs[0]));
    gy = (int)rintf(__fdiv_rn(__fsub_rn(cr[4], cr[1]), vs[1]));
    gz = (int)rintf(__fdiv_rn(__fsub_rn(cr[5], cr[2]), vs[2]));
}

// Pass K: quantize; histogram buckets of the flipped wrapped key; stash payload.
// Also clears g_cnt (read only by later passS2/passT — safe).
__global__ void passK(const float* __restrict__ pts, const float* __restrict__ vs,
                      const float* __restrict__ cr, int n) {
    int i = blockIdx.x * 256 + threadIdx.x;
    if (i < MAXV) g_cnt[i] = 0;
    if (i >= n) return;
    int gx, gy, gz;
    grid_dims(vs, cr, gx, gy, gz);
    float m0 = cr[0], m1 = cr[1], m2 = cr[2];
    size_t b = (size_t)i * 5;
    float px = pts[b + 0], py = pts[b + 1], pz = pts[b + 2];
    int cx = (int)floorf(__fdiv_rn(__fsub_rn(px, m0), vs[0]));
    int cy = (int)floorf(__fdiv_rn(__fsub_rn(py, m1), vs[1]));
    int cz = (int)floorf(__fdiv_rn(__fsub_rn(pz, m2), vs[2]));
    bool valid = (cx >= 0) && (cx < gx) && (cy >= 0) && (cy < gy) &&
                 (cz >= 0) && (cz < gz);
    int total = gx * gy * gz;                        // 82,944,000 fits int32
    int lin = valid ? ((cx * gy + cy) * gz + cz) : total;
    unsigned fk = ((unsigned)lin * (unsigned)n + (unsigned)i) ^ 0x80000000u;
    atomicAdd(&g_bcnt[fk >> BSHIFT], 1);
    g_val[i] = ((unsigned long long)(unsigned)lin << IDX_BITS) | (unsigned)i;
}

// Pass SC: scatter each point into its bucket region (intra-bucket order fixed
// deterministically by passLS). Mutates g_boff[b] into bucket END offsets.
__global__ void passSC(int n) {
    int i = blockIdx.x * 256 + threadIdx.x;
    if (i >= n) return;
    unsigned long long v = g_val[i];
    unsigned fk = fkey_of(v, (unsigned)n);
    int pos = atomicAdd(&g_boff[fk >> BSHIFT], 1);
    g_sorted[pos] = v;
}

// Pass LS: per-bucket insertion sort by (flipped key, idx). Afterwards g_sorted
// is in exact (signed wrapped key, original index) order == the reference's
// jnp.argsort(lin*N+idx) with int32 wrap.
__global__ void passLS(int n) {
    unsigned b = blockIdx.x * 256 + threadIdx.x;
    if (b >= NBUCKET) return;
    int end = g_boff[b];                  // mutated = exclusive end of bucket b
    int start = (b == 0) ? 0 : g_boff[b - 1];
    if (end - start < 2) return;
    unsigned un = (unsigned)n;
    for (int a = start + 1; a < end; a++) {
        unsigned long long v = g_sorted[a];
        unsigned kv = fkey_of(v, un);
        unsigned iv = (unsigned)(v & IDX_MASK);
        int c = a - 1;
        while (c >= start) {
            unsigned long long w = g_sorted[c];
            unsigned kw = fkey_of(w, un);
            if (kw > kv || (kw == kv && (unsigned)(w & IDX_MASK) > iv)) {
                g_sorted[c + 1] = w;
                c--;
            } else break;
        }
        g_sorted[c + 1] = v;
    }
}

// Pass S1 (sorted order): is_head = valid && lin != prev lin; scatter to idx order.
__global__ void passS1(const float* __restrict__ vs, const float* __restrict__ cr, int n) {
    int p = blockIdx.x * 256 + threadIdx.x;
    if (p >= n) return;
    int gx, gy, gz;
    grid_dims(vs, cr, gx, gy, gz);
    int total = gx * gy * gz;
    unsigned long long v = g_sorted[p];
    int lin  = (int)(v >> IDX_BITS);
    int linp = (p > 0) ? (int)(g_sorted[p - 1] >> IDX_BITS) : -1;
    g_fidx[(unsigned)(v & IDX_MASK)] = (lin < total) && (lin != linp);
}

// Pass S2 (sorted order): backward-walk to run head (runs tiny); slot = p-h;
// vox = rank of head's original index among heads; scatter outputs.
__global__ void passS2(const float* __restrict__ pts, const float* __restrict__ vs,
                       const float* __restrict__ cr, int n, float* __restrict__ out) {
    int p = blockIdx.x * 256 + threadIdx.x;
    if (p >= n) return;
    int gx, gy, gz;
    grid_dims(vs, cr, gx, gy, gz);
    int total = gx * gy * gz;
    unsigned long long v = g_sorted[p];
    int lin = (int)(v >> IDX_BITS);
    if (lin >= total) return;                 // invalid point
    int h = p;                                // walk back to run head
    while (h > 0 && (int)(g_sorted[h - 1] >> IDX_BITS) == lin) h--;
    int slot = p - h;
    int head_orig = (int)(g_sorted[h] & IDX_MASK);
    int vox = g_rank[head_orig];
    if (vox >= MAXV) return;
    atomicAdd(&g_cnt[vox], 1);
    if (slot < MAXP) {
        int o = (int)(v & IDX_MASK);
        const float* src = pts + (size_t)o * 5;
        float* dst = out + OFF_VOX + (size_t)vox * (MAXP * 5) + slot * 5;
        dst[0] = src[0]; dst[1] = src[1]; dst[2] = src[2];
        dst[3] = src[3]; dst[4] = src[4];
    }
    if (p == h) {                             // head writes coors (z, y, x)
        int cz = lin % gz;
        int r = lin / gz;
        int cy = r % gy;
        int cx = r / gy;
        float* oc = out + OFF_COORS + (size_t)vox * 3;
        oc[0] = (float)cz;
        oc[1] = (float)cy;
        oc[2] = (float)cx;
    }
}

// Pass T: counts -> min(cnt,10) as float; zero coors tail rows; voxel_num.
__global__ void passT(float* __restrict__ out, int n) {
    int v = blockIdx.x * blockDim.x + threadIdx.x;
    int H = g_rank[n - 1] + g_fidx[n - 1];
    int vnum = min(H, MAXV);
    if (v < MAXV) {
        out[OFF_CNT + v] = (float)min(g_cnt[v], MAXP);
        if (v >= vnum) {                      // no head wrote this coors row
            float* oc = out + OFF_COORS + (size_t)v * 3;
            oc[0] = 0.f; oc[1] = 0.f; oc[2] = 0.f;
        }
    }
    if (v == 0) out[OFF_VNUM] = (float)vnum;
}

extern "C" void kernel_launch(void* const* d_in, const int* in_sizes, int n_in,
                              void* d_out, int out_size) {
    // Disambiguate inputs by element count: points = largest,
    // voxel_size = 3 elements, coors_range = 6 elements.
    const float* pts = nullptr;
    const float* vs  = nullptr;
    const float* cr  = nullptr;
    int pts_size = -1;
    for (int k = 0; k < n_in; k++) {
        int sz = in_sizes[k];
        if (sz == 3) vs = (const float*)d_in[k];
        else if (sz == 6) cr = (const float*)d_in[k];
        if (sz > pts_size) { pts_size = sz; pts = (const float*)d_in[k]; }
    }
    int n = pts_size / 5;
    float* out = (float*)d_out;

    void *p_bcnt, *p_boff, *p_fidx, *p_rank, *p_tmp;
    cudaGetSymbolAddress(&p_bcnt, g_bcnt);
    cudaGetSymbolAddress(&p_boff, g_boff);
    cudaGetSymbolAddress(&p_fidx, g_fidx);
    cudaGetSymbolAddress(&p_rank, g_rank);
    cudaGetSymbolAddress(&p_tmp, g_cubtmp);

    // Zero only the voxels region (coors tails handled by passT; counts/vnum
    // fully written by passT; voxels slots >= run length need these zeros).
    cudaMemsetAsync(out, 0, (size_t)(MAXV * MAXP * 5) * sizeof(float), 0);
    cudaMemsetAsync(p_bcnt, 0, sizeof(int) * NBUCKET, 0);

    int nb = (n + 255) / 256;
    passK<<<nb, 256>>>(pts, vs, cr, n);

    size_t tb = sizeof(g_cubtmp);
    cub::DeviceScan::ExclusiveSum(p_tmp, tb, (const int*)p_bcnt,
                                  (int*)p_boff, (int)NBUCKET, 0);

    passSC<<<nb, 256>>>(n);
    passLS<<<(NBUCKET + 255) / 256, 256>>>(n);
    passS1<<<nb, 256>>>(vs, cr, n);

    tb = sizeof(g_cubtmp);
    cub::DeviceScan::ExclusiveSum(p_tmp, tb, (const int*)p_fidx,
                                  (int*)p_rank, n, 0);

    passS2<<<nb, 256>>>(pts, vs, cr, n, out);
    passT<<<(MAXV + 255) / 256, 256>>>(out, n);
}

// round 17
// speedup vs baseline: 1.3391x; 1.3391x over previous
#include <cuda_runtime.h>
#include <cub/cub.cuh>
#include <cstdint>

#define MAXP 10
#define MAXV 160000
#define NCAP (1 << 21)
#define IDX_BITS 21
#define IDX_MASK ((1u << IDX_BITS) - 1u)
#define BBITS 21
#define NBUCKET (1u << BBITS)
#define BSHIFT (32 - BBITS)   // 11: bucket = flipped_key >> 11

// Output layout (tuple order): voxels | coors | num_points | voxel_num
#define OFF_VOX   0
#define OFF_COORS 8000000
#define OFF_CNT   8480000
#define OFF_VNUM  8640000

// ---- device scratch (static globals: allowed; no runtime allocation) ----
__device__ unsigned long long g_val[NCAP];      // per-point (lin << 21 | idx)
__device__ unsigned long long g_sorted[NCAP];   // bucket-sorted, then locally sorted
__device__ int g_bcnt[NBUCKET];                 // bucket histogram (zeroed per run)
__device__ int g_boff[NBUCKET];                 // exclusive offsets; mutated to ENDS
__device__ int g_fidx[NCAP];                    // head flag in ORIGINAL index order
__device__ int g_rank[NCAP];                    // exclusive prefix sum of g_fidx
__device__ int g_headpos[MAXV];                 // sorted position of voxel head (-1 = none)
__device__ int g_cnt[MAXV];                     // zeroed per run
__device__ __align__(256) unsigned char g_cubtmp[8u << 20];

// Flipped (sign-bit-toggled) wrapped int32 key: unsigned order == signed order.
__device__ __forceinline__ unsigned fkey_of(unsigned long long v, unsigned n) {
    return ((unsigned)(v >> IDX_BITS) * n + (unsigned)(v & IDX_MASK)) ^ 0x80000000u;
}

// IEEE f32 quantization (bit-matches XLA CPU float32; immune to fast-math).
__device__ __forceinline__ void grid_dims(const float* __restrict__ vs,
                                          const float* __restrict__ cr,
                                          int& gx, int& gy, int& gz) {
    gx = (int)rintf(__fdiv_rn(__fsub_rn(cr[3], cr[0]), vs[0]));
    gy = (int)rintf(__fdiv_rn(__fsub_rn(cr[4], cr[1]), vs[1]));
    gz = (int)rintf(__fdiv_rn(__fsub_rn(cr[5], cr[2]), vs[2]));
}

// Pass K: quantize; histogram buckets of the flipped wrapped key; stash payload.
__global__ void passK(const float* __restrict__ pts, const float* __restrict__ vs,
                      const float* __restrict__ cr, int n) {
    int i = blockIdx.x * 256 + threadIdx.x;
    if (i >= n) return;
    int gx, gy, gz;
    grid_dims(vs, cr, gx, gy, gz);
    float m0 = cr[0], m1 = cr[1], m2 = cr[2];
    size_t b = (size_t)i * 5;
    float px = pts[b + 0], py = pts[b + 1], pz = pts[b + 2];
    int cx = (int)floorf(__fdiv_rn(__fsub_rn(px, m0), vs[0]));
    int cy = (int)floorf(__fdiv_rn(__fsub_rn(py, m1), vs[1]));
    int cz = (int)floorf(__fdiv_rn(__fsub_rn(pz, m2), vs[2]));
    bool valid = (cx >= 0) && (cx < gx) && (cy >= 0) && (cy < gy) &&
                 (cz >= 0) && (cz < gz);
    int total = gx * gy * gz;                        // 82,944,000 fits int32
    int lin = valid ? ((cx * gy + cy) * gz + cz) : total;
    unsigned fk = ((unsigned)lin * (unsigned)n + (unsigned)i) ^ 0x80000000u;
    atomicAdd(&g_bcnt[fk >> BSHIFT], 1);
    g_val[i] = ((unsigned long long)(unsigned)lin << IDX_BITS) | (unsigned)i;
}

// Pass SC: scatter each point into its bucket region (intra-bucket order fixed
// deterministically by passLS). Mutates g_boff[b] into bucket END offsets.
__global__ void passSC(int n) {
    int i = blockIdx.x * 256 + threadIdx.x;
    if (i >= n) return;
    unsigned long long v = g_val[i];
    unsigned fk = fkey_of(v, (unsigned)n);
    int pos = atomicAdd(&g_boff[fk >> BSHIFT], 1);
    g_sorted[pos] = v;
}

// Pass LS: per-bucket insertion sort by (flipped key, idx). Afterwards g_sorted
// is in exact (signed wrapped key, original index) order == the reference's
// jnp.argsort(lin*N+idx) with int32 wrap.
__global__ void passLS(int n) {
    unsigned b = blockIdx.x * 256 + threadIdx.x;
    if (b >= NBUCKET) return;
    int end = g_boff[b];                  // mutated = exclusive end of bucket b
    int start = (b == 0) ? 0 : g_boff[b - 1];
    if (end - start < 2) return;
    unsigned un = (unsigned)n;
    for (int a = start + 1; a < end; a++) {
        unsigned long long v = g_sorted[a];
        unsigned kv = fkey_of(v, un);
        unsigned iv = (unsigned)(v & IDX_MASK);
        int c = a - 1;
        while (c >= start) {
            unsigned long long w = g_sorted[c];
            unsigned kw = fkey_of(w, un);
            if (kw > kv || (kw == kv && (unsigned)(w & IDX_MASK) > iv)) {
                g_sorted[c + 1] = w;
                c--;
            } else break;
        }
        g_sorted[c + 1] = v;
    }
}

// Pass S1 (sorted order): is_head = valid && lin != prev lin; scatter to idx order.
__global__ void passS1(const float* __restrict__ vs, const float* __restrict__ cr, int n) {
    int p = blockIdx.x * 256 + threadIdx.x;
    if (p >= n) return;
    int gx, gy, gz;
    grid_dims(vs, cr, gx, gy, gz);
    int total = gx * gy * gz;
    unsigned long long v = g_sorted[p];
    int lin  = (int)(v >> IDX_BITS);
    int linp = (p > 0) ? (int)(g_sorted[p - 1] >> IDX_BITS) : -1;
    g_fidx[(unsigned)(v & IDX_MASK)] = (lin < total) && (lin != linp);
}

// Pass S2 (sorted order): backward-walk to run head (runs tiny); counts via
// atomicAdd; heads record sorted head position + write coors (z,y,x).
__global__ void passS2(const float* __restrict__ vs, const float* __restrict__ cr,
                       int n, float* __restrict__ out) {
    int p = blockIdx.x * 256 + threadIdx.x;
    if (p >= n) return;
    int gx, gy, gz;
    grid_dims(vs, cr, gx, gy, gz);
    int total = gx * gy * gz;
    unsigned long long v = g_sorted[p];
    int lin = (int)(v >> IDX_BITS);
    if (lin >= total) return;                 // invalid point
    int h = p;                                // walk back to run head
    while (h > 0 && (int)(g_sorted[h - 1] >> IDX_BITS) == lin) h--;
    int head_orig = (int)(g_sorted[h] & IDX_MASK);
    int vox = g_rank[head_orig];
    if (vox >= MAXV) return;
    atomicAdd(&g_cnt[vox], 1);
    if (p == h) {                             // head: record position, write coors
        g_headpos[vox] = h;
        int cz = lin % gz;
        int r = lin / gz;
        int cy = r % gy;
        int cx = r / gy;
        float* oc = out + OFF_COORS + (size_t)vox * 3;
        oc[0] = (float)cz;
        oc[1] = (float)cy;
        oc[2] = (float)cx;
    }
}

// Pass V: gather-assemble the ENTIRE voxels region with coalesced writes.
// CRITICAL: slot is filled only if positions h..h+slot form a CONTIGUOUS
// same-lin run prefix (same-lin runs recur later in wrapped order; a bare
// lin-equality check at h+slot leaks those later runs into empty slots).
__global__ void passV(const float* __restrict__ pts, int n, float* __restrict__ out) {
    int t = blockIdx.x * 256 + threadIdx.x;
    if (t >= MAXV * MAXP) return;
    int vox = t / MAXP;
    int slot = t - vox * MAXP;
    float f0 = 0.f, f1 = 0.f, f2 = 0.f, f3 = 0.f, f4 = 0.f;
    int h = g_headpos[vox];
    if (h >= 0 && h + slot < n) {
        int lin = (int)(g_sorted[h] >> IDX_BITS);
        bool ok = true;
        for (int j = 1; j <= slot; j++) {          // verify contiguous run prefix
            if ((int)(g_sorted[h + j] >> IDX_BITS) != lin) { ok = false; break; }
        }
        if (ok) {
            int o = (int)(g_sorted[h + slot] & IDX_MASK);
            const float* src = pts + (size_t)o * 5;
            f0 = src[0]; f1 = src[1]; f2 = src[2]; f3 = src[3]; f4 = src[4];
        }
    }
    float* dst = out + OFF_VOX + (size_t)t * 5;
    dst[0] = f0; dst[1] = f1; dst[2] = f2; dst[3] = f3; dst[4] = f4;
}

// Pass T: counts -> min(cnt,10) as float; zero coors tail rows; voxel_num.
__global__ void passT(float* __restrict__ out, int n) {
    int v = blockIdx.x * blockDim.x + threadIdx.x;
    int H = g_rank[n - 1] + g_fidx[n - 1];
    int vnum = min(H, MAXV);
    if (v < MAXV) {
        out[OFF_CNT + v] = (float)min(g_cnt[v], MAXP);
        if (v >= vnum) {                      // no head wrote this coors row
            float* oc = out + OFF_COORS + (size_t)v * 3;
            oc[0] = 0.f; oc[1] = 0.f; oc[2] = 0.f;
        }
    }
    if (v == 0) out[OFF_VNUM] = (float)vnum;
}

extern "C" void kernel_launch(void* const* d_in, const int* in_sizes, int n_in,
                              void* d_out, int out_size) {
    // Disambiguate inputs by element count: points = largest,
    // voxel_size = 3 elements, coors_range = 6 elements.
    const float* pts = nullptr;
    const float* vs  = nullptr;
    const float* cr  = nullptr;
    int pts_size = -1;
    for (int k = 0; k < n_in; k++) {
        int sz = in_sizes[k];
        if (sz == 3) vs = (const float*)d_in[k];
        else if (sz == 6) cr = (const float*)d_in[k];
        if (sz > pts_size) { pts_size = sz; pts = (const float*)d_in[k]; }
    }
    int n = pts_size / 5;
    float* out = (float*)d_out;

    void *p_bcnt, *p_boff, *p_fidx, *p_rank, *p_cnt, *p_hp, *p_tmp;
    cudaGetSymbolAddress(&p_bcnt, g_bcnt);
    cudaGetSymbolAddress(&p_boff, g_boff);
    cudaGetSymbolAddress(&p_fidx, g_fidx);
    cudaGetSymbolAddress(&p_rank, g_rank);
    cudaGetSymbolAddress(&p_cnt, g_cnt);
    cudaGetSymbolAddress(&p_hp, g_headpos);
    cudaGetSymbolAddress(&p_tmp, g_cubtmp);

    cudaMemsetAsync(p_bcnt, 0, sizeof(int) * NBUCKET, 0);
    cudaMemsetAsync(p_cnt, 0, sizeof(int) * MAXV, 0);
    cudaMemsetAsync(p_hp, 0xFF, sizeof(int) * MAXV, 0);

    int nb = (n + 255) / 256;
    passK<<<nb, 256>>>(pts, vs, cr, n);

    size_t tb = sizeof(g_cubtmp);
    cub::DeviceScan::ExclusiveSum(p_tmp, tb, (const int*)p_bcnt,
                                  (int*)p_boff, (int)NBUCKET, 0);

    passSC<<<nb, 256>>>(n);
    passLS<<<(NBUCKET + 255) / 256, 256>>>(n);
    passS1<<<nb, 256>>>(vs, cr, n);

    tb = sizeof(g_cubtmp);
    cub::DeviceScan::ExclusiveSum(p_tmp, tb, (const int*)p_fidx,
                                  (int*)p_rank, n, 0);

    passS2<<<nb, 256>>>(vs, cr, n, out);
    passV<<<(MAXV * MAXP + 255) / 256, 256>>>(pts, n, out);
    passT<<<(MAXV + 255) / 256, 256>>>(out, n);
}